// round 12
// baseline (speedup 1.0000x reference)
#include <cuda_runtime.h>
#include <cuda_bf16.h>
#include <cuda_fp16.h>
#include <math.h>
#include <cstdint>

#define NROWS 8192
#define DIM   512
#define TOPK  12
#define THETA 10.0f

// ---------------- device scratch (no allocation allowed) -------------------
__device__ int8_t g_q[(size_t)NROWS * DIM];              // 4 MB quantized rows
__device__ float  g_scale[NROWS];                        // 1/||q|| per row
__device__ __half g_sim[(size_t)NROWS * NROWS];          // 128 MB similarity

__device__ __forceinline__ uint32_t smem_u32(const void* p) {
    uint32_t a;
    asm("{ .reg .u64 t; cvta.to.shared.u64 t, %1; cvt.u32.u64 %0, t; }"
        : "=r"(a) : "l"(p));
    return a;
}
__device__ __forceinline__ void cp_async16(uint32_t dst, const void* src) {
    asm volatile("cp.async.cg.shared.global [%0], [%1], 16;" :: "r"(dst), "l"(src));
}
__device__ __forceinline__ void cp_commit() {
    asm volatile("cp.async.commit_group;" ::: "memory");
}
template <int N>
__device__ __forceinline__ void cp_wait() {
    asm volatile("cp.async.wait_group %0;" :: "n"(N) : "memory");
}
__device__ __forceinline__ void ldsm_x4(uint32_t* r, uint32_t addr) {
    asm volatile("ldmatrix.sync.aligned.m8n8.x4.shared.b16 {%0,%1,%2,%3}, [%4];"
                 : "=r"(r[0]), "=r"(r[1]), "=r"(r[2]), "=r"(r[3]) : "r"(addr));
}
__device__ __forceinline__ void imma16832(int* c, const uint32_t* a,
                                          uint32_t b0, uint32_t b1) {
    asm volatile(
        "mma.sync.aligned.m16n8k32.row.col.s32.s8.s8.s32 "
        "{%0,%1,%2,%3}, {%4,%5,%6,%7}, {%8,%9}, {%0,%1,%2,%3};"
        : "+r"(c[0]), "+r"(c[1]), "+r"(c[2]), "+r"(c[3])
        : "r"(a[0]), "r"(a[1]), "r"(a[2]), "r"(a[3]), "r"(b0), "r"(b1));
}

// ---------------------------------------------------------------------------
// Kernel 1: normalize -> int8 quantize (via int; `char` is unsigned on aarch64)
// ---------------------------------------------------------------------------
__global__ __launch_bounds__(256) void quant_kernel(const float* __restrict__ h) {
    int row = blockIdx.x;
    int tid = threadIdx.x;
    const float* hr = h + (size_t)row * DIM;

    float v0 = hr[2 * tid];
    float v1 = hr[2 * tid + 1];
    float s = v0 * v0 + v1 * v1;
    #pragma unroll
    for (int off = 16; off > 0; off >>= 1) s += __shfl_xor_sync(~0u, s, off);

    __shared__ float red[8];
    if ((tid & 31) == 0) red[tid >> 5] = s;
    __syncthreads();
    if (tid < 32) {
        float t = (tid < 8) ? red[tid] : 0.0f;
        #pragma unroll
        for (int off = 4; off > 0; off >>= 1) t += __shfl_xor_sync(~0u, t, off);
        if (tid == 0) red[0] = t;
    }
    __syncthreads();
    float inv = 127.0f / fmaxf(sqrtf(red[0]), 1e-8f);

    int qi0 = (int)rintf(fminf(fmaxf(v0 * inv, -127.0f), 127.0f));
    int qi1 = (int)rintf(fminf(fmaxf(v1 * inv, -127.0f), 127.0f));
    float q0 = (float)qi0, q1 = (float)qi1;

    float sq = q0 * q0 + q1 * q1;
    #pragma unroll
    for (int off = 16; off > 0; off >>= 1) sq += __shfl_xor_sync(~0u, sq, off);
    __syncthreads();
    if ((tid & 31) == 0) red[tid >> 5] = sq;
    __syncthreads();
    if (tid < 32) {
        float t = (tid < 8) ? red[tid] : 0.0f;
        #pragma unroll
        for (int off = 4; off > 0; off >>= 1) t += __shfl_xor_sync(~0u, t, off);
        if (tid == 0) g_scale[row] = (t > 0.0f) ? rsqrtf(t) : 0.0f;
    }

    uint16_t packed = (uint16_t)((qi0 & 0xFF) | ((qi1 & 0xFF) << 8));
    *reinterpret_cast<uint16_t*>(g_q + (size_t)row * DIM + 2 * tid) = packed;
}

// ---------------------------------------------------------------------------
// Kernel 2: Sim = cos(q_a, q_b) via INT8 IMMA + ldmatrix, upper-tri tiles only
// ---------------------------------------------------------------------------
#define KC 64                        // K bytes per stage
#define NITER (DIM / KC)             // 8
#define ROWB 80                      // smem row stride (64B data + 16B pad)
#define STAGE_BYTES (2 * 128 * ROWB) // 20480
#define GSMEM (3 * STAGE_BYTES)      // 61440

__device__ __forceinline__ void load_stage(uint32_t sbase, int buf, int c,
                                           int tid, int bm, int bn) {
    uint32_t sA = sbase + buf * STAGE_BYTES;
    uint32_t sB = sA + 128 * ROWB;
    const char* gb = (const char*)g_q;
    #pragma unroll
    for (int p = 0; p < 2; p++) {
        int i = tid + p * 256;
        int row = i >> 2, seg = i & 3;
        size_t koff = (size_t)c * KC + seg * 16;
        cp_async16(sA + row * ROWB + seg * 16, gb + (size_t)(bm + row) * DIM + koff);
        cp_async16(sB + row * ROWB + seg * 16, gb + (size_t)(bn + row) * DIM + koff);
    }
}

__global__ __launch_bounds__(256) void gemm_kernel() {
    const int I = blockIdx.y, J = blockIdx.x;
    if (J < I) return;
    const int bm = I * 128, bn = J * 128;

    extern __shared__ char smem[];
    const uint32_t sbase = smem_u32(smem);
    const int tid = threadIdx.x;
    const int lane = tid & 31;
    const int wid = tid >> 5;
    const int warpM = wid >> 2;              // 0..1 -> 64 rows
    const int warpN = wid & 3;               // 0..3 -> 32 cols
    const int g   = lane >> 2;               // groupID 0..7
    const int tig = lane & 3;                // thread-in-group 0..3

    int acc[4][4][4];
    #pragma unroll
    for (int mi = 0; mi < 4; mi++)
        #pragma unroll
        for (int ni = 0; ni < 4; ni++)
            #pragma unroll
            for (int q = 0; q < 4; q++) acc[mi][ni][q] = 0;

    load_stage(sbase, 0, 0, tid, bm, bn); cp_commit();
    load_stage(sbase, 1, 1, tid, bm, bn); cp_commit();

    // ldmatrix lane addressing: lane 0-15 -> rows of first m8n8, lane>>4 -> 16B half
    const uint32_t aLane = (uint32_t)((warpM * 64 + (lane & 15)) * ROWB + (lane >> 4) * 16);
    const uint32_t bLane = (uint32_t)(128 * ROWB + (warpN * 32 + (lane & 15)) * ROWB + (lane >> 4) * 16);

    for (int c = 0; c < NITER; c++) {
        if (c + 2 < NITER) cp_wait<1>(); else cp_wait<0>();
        __syncthreads();
        if (c + 2 < NITER) load_stage(sbase, (c + 2) % 3, c + 2, tid, bm, bn);
        cp_commit();

        const uint32_t sbuf = sbase + (c % 3) * STAGE_BYTES;
        #pragma unroll
        for (int ks = 0; ks < 2; ks++) {        // two k32 slices per 64B chunk
            uint32_t a[4][4], b[2][4];
            #pragma unroll
            for (int mi = 0; mi < 4; mi++)
                ldsm_x4(a[mi], sbuf + aLane + mi * (16 * ROWB) + ks * 32);
            #pragma unroll
            for (int nj = 0; nj < 2; nj++)
                ldsm_x4(b[nj], sbuf + bLane + nj * (16 * ROWB) + ks * 32);
            // fragment map: r0=n0-7/k-lo, r1=n8-15/k-lo, r2=n0-7/k-hi, r3=n8-15/k-hi
            // IMMA B pair = same n-cols, k-lo then k-hi -> (r[p], r[p+2])
            #pragma unroll
            for (int mi = 0; mi < 4; mi++)
                #pragma unroll
                for (int ni = 0; ni < 4; ni++) {
                    const int nj = ni >> 1, pair = ni & 1;
                    imma16832(acc[mi][ni], a[mi], b[nj][pair], b[nj][pair + 2]);
                }
        }
    }

    // epilogue: scale to cosine, fp16 store; off-diagonal also transposed
    const int r0 = bm + warpM * 64 + g;
    const int c0 = bn + warpN * 32 + tig * 2;
    const bool offdiag = (I != J);

    float sAlo[4], sAhi[4], sB0[4], sB1[4];
    #pragma unroll
    for (int mi = 0; mi < 4; mi++) {
        sAlo[mi] = g_scale[r0 + mi * 16];
        sAhi[mi] = g_scale[r0 + mi * 16 + 8];
    }
    #pragma unroll
    for (int ni = 0; ni < 4; ni++) {
        sB0[ni] = g_scale[c0 + ni * 8];
        sB1[ni] = g_scale[c0 + ni * 8 + 1];
    }

    #pragma unroll
    for (int mi = 0; mi < 4; mi++) {
        #pragma unroll
        for (int ni = 0; ni < 4; ni++) {
            const int r = r0 + mi * 16;
            const int cc = c0 + ni * 8;
            float d0 = (float)acc[mi][ni][0] * sAlo[mi] * sB0[ni];
            float d1 = (float)acc[mi][ni][1] * sAlo[mi] * sB1[ni];
            float d2 = (float)acc[mi][ni][2] * sAhi[mi] * sB0[ni];
            float d3 = (float)acc[mi][ni][3] * sAhi[mi] * sB1[ni];
            *reinterpret_cast<__half2*>(g_sim + (size_t)r * NROWS + cc) =
                make_half2(__float2half_rn(d0), __float2half_rn(d1));
            *reinterpret_cast<__half2*>(g_sim + (size_t)(r + 8) * NROWS + cc) =
                make_half2(__float2half_rn(d2), __float2half_rn(d3));
            if (offdiag) {
                __half* q0 = g_sim + (size_t)cc * NROWS + r;
                __half* q1 = g_sim + (size_t)(cc + 1) * NROWS + r;
                q0[0] = __float2half_rn(d0); q1[0] = __float2half_rn(d1);
                q0[8] = __float2half_rn(d2); q1[8] = __float2half_rn(d3);
            }
        }
    }
}

// ---------------------------------------------------------------------------
// Kernel 3: per-row top-12 (fp16 sims) -> softmax -> weighted gather of h
// ---------------------------------------------------------------------------
__global__ __launch_bounds__(256) void topk_kernel(const float* __restrict__ h,
                                                   float* __restrict__ out) {
    int row = blockIdx.x;
    int tid = threadIdx.x;
    const __half* sim = g_sim + (size_t)row * NROWS;

    float v[TOPK]; int ix[TOPK];
    #pragma unroll
    for (int k = 0; k < TOPK; k++) { v[k] = -INFINITY; ix[k] = 0x7FFFFFFF; }

    #pragma unroll
    for (int t = 0; t < 4; t++) {
        int base8 = t * 256 + tid;               // uint4 index (8 halfs)
        uint4 u = reinterpret_cast<const uint4*>(sim)[base8];
        int j0 = base8 * 8;
        uint32_t w[4] = {u.x, u.y, u.z, u.w};
        #pragma unroll
        for (int e = 0; e < 8; e++) {
            __half hv = ((const __half*)w)[e];
            float val = __half2float(hv);
            if (val > v[TOPK - 1]) {
                int p = TOPK - 1;
                #pragma unroll
                for (int s = TOPK - 1; s > 0; s--) {
                    if (v[s - 1] < val) { v[s] = v[s - 1]; ix[s] = ix[s - 1]; p = s - 1; }
                }
                v[p] = val; ix[p] = j0 + e;
            }
        }
    }

    __shared__ float sV[256][TOPK];
    __shared__ int   sI[256][TOPK];
    #pragma unroll
    for (int k = 0; k < TOPK; k++) { sV[tid][k] = v[k]; sI[tid][k] = ix[k]; }

    for (int stride = 128; stride > 0; stride >>= 1) {
        __syncthreads();
        if (tid < stride) {
            float mv[TOPK]; int mi[TOPK];
            int a = 0, b = 0;
            #pragma unroll
            for (int k = 0; k < TOPK; k++) {
                float va = sV[tid][a], vb = sV[tid + stride][b];
                int   ia = sI[tid][a], ib = sI[tid + stride][b];
                bool takeA = (va > vb) || (va == vb && ia < ib);
                if (takeA) { mv[k] = va; mi[k] = ia; a++; }
                else       { mv[k] = vb; mi[k] = ib; b++; }
            }
            #pragma unroll
            for (int k = 0; k < TOPK; k++) { sV[tid][k] = mv[k]; sI[tid][k] = mi[k]; }
        }
    }
    __syncthreads();

    __shared__ float sBeta[TOPK];
    __shared__ int   sIdx[TOPK];
    if (tid == 0) {
        float m = sV[0][0];
        float e[TOPK], sum = 0.0f;
        #pragma unroll
        for (int k = 0; k < TOPK; k++) { e[k] = expf(THETA * (sV[0][k] - m)); sum += e[k]; }
        float inv = 1.0f / sum;
        #pragma unroll
        for (int k = 0; k < TOPK; k++) { sBeta[k] = e[k] * inv; sIdx[k] = sI[0][k]; }
    }
    __syncthreads();

    float beta[TOPK]; const float* hp[TOPK];
    #pragma unroll
    for (int k = 0; k < TOPK; k++) { beta[k] = sBeta[k]; hp[k] = h + (size_t)sIdx[k] * DIM; }

    #pragma unroll
    for (int d = tid; d < DIM; d += 256) {
        float acc = 0.0f;
        #pragma unroll
        for (int k = 0; k < TOPK; k++) acc += beta[k] * hp[k][d];
        out[(size_t)row * DIM + d] = acc;
    }
}

// ---------------------------------------------------------------------------
extern "C" void kernel_launch(void* const* d_in, const int* in_sizes, int n_in,
                              void* d_out, int out_size) {
    const float* h = (const float*)d_in[0];
    float* out = (float*)d_out;

    cudaFuncSetAttribute(gemm_kernel, cudaFuncAttributeMaxDynamicSharedMemorySize, GSMEM);

    quant_kernel<<<NROWS, 256>>>(h);
    gemm_kernel<<<dim3(NROWS / 128, NROWS / 128), 256, GSMEM>>>();
    topk_kernel<<<NROWS, 256>>>(h, out);
}

// round 13
// speedup vs baseline: 2.0128x; 2.0128x over previous
#include <cuda_runtime.h>
#include <cuda_bf16.h>
#include <cuda_fp16.h>
#include <math.h>
#include <cstdint>

#define NROWS 8192
#define DIM   512
#define TOPK  12
#define THETA 10.0f

// ---------------- device scratch (no allocation allowed) -------------------
__device__ __nv_bfloat16 g_hn[NROWS * DIM];              // 8 MB normalized bf16
__device__ __half g_sim[(size_t)NROWS * NROWS];          // 128 MB similarity

__device__ __forceinline__ uint32_t smem_u32(const void* p) {
    uint32_t a;
    asm("{ .reg .u64 t; cvta.to.shared.u64 t, %1; cvt.u32.u64 %0, t; }"
        : "=r"(a) : "l"(p));
    return a;
}
__device__ __forceinline__ void cp_async16(uint32_t dst, const void* src) {
    asm volatile("cp.async.cg.shared.global [%0], [%1], 16;" :: "r"(dst), "l"(src));
}
__device__ __forceinline__ void cp_commit() {
    asm volatile("cp.async.commit_group;" ::: "memory");
}
template <int N>
__device__ __forceinline__ void cp_wait() {
    asm volatile("cp.async.wait_group %0;" :: "n"(N) : "memory");
}
__device__ __forceinline__ void ldsm_x4(uint32_t* r, uint32_t addr) {
    asm volatile("ldmatrix.sync.aligned.m8n8.x4.shared.b16 {%0,%1,%2,%3}, [%4];"
                 : "=r"(r[0]), "=r"(r[1]), "=r"(r[2]), "=r"(r[3]) : "r"(addr));
}
__device__ __forceinline__ void mma16816(float* c, const uint32_t* a,
                                         uint32_t b0, uint32_t b1) {
    asm volatile(
        "mma.sync.aligned.m16n8k16.row.col.f32.bf16.bf16.f32 "
        "{%0,%1,%2,%3}, {%4,%5,%6,%7}, {%8,%9}, {%0,%1,%2,%3};"
        : "+f"(c[0]), "+f"(c[1]), "+f"(c[2]), "+f"(c[3])
        : "r"(a[0]), "r"(a[1]), "r"(a[2]), "r"(a[3]), "r"(b0), "r"(b1));
}

// ---------------------------------------------------------------------------
// Kernel 1: row L2 norms -> normalized bf16 rows (proven R1/R4 version)
// ---------------------------------------------------------------------------
__global__ __launch_bounds__(256) void norm_kernel(const float* __restrict__ h) {
    int row = blockIdx.x;
    int tid = threadIdx.x;
    const float* hr = h + (size_t)row * DIM;

    float v0 = hr[tid];
    float v1 = hr[tid + 256];
    float s = v0 * v0 + v1 * v1;
    #pragma unroll
    for (int off = 16; off > 0; off >>= 1) s += __shfl_xor_sync(~0u, s, off);

    __shared__ float red[8];
    if ((tid & 31) == 0) red[tid >> 5] = s;
    __syncthreads();
    if (tid < 32) {
        float t = (tid < 8) ? red[tid] : 0.0f;
        #pragma unroll
        for (int off = 4; off > 0; off >>= 1) t += __shfl_xor_sync(~0u, t, off);
        if (tid == 0) red[0] = t;
    }
    __syncthreads();
    float inv = 1.0f / fmaxf(sqrtf(red[0]), 1e-8f);
    g_hn[(size_t)row * DIM + tid]       = __float2bfloat16(v0 * inv);
    g_hn[(size_t)row * DIM + tid + 256] = __float2bfloat16(v1 * inv);
}

// ---------------------------------------------------------------------------
// Kernel 2: Sim = hn @ hn^T, upper-triangular tiles only (symmetric), HMMA
//   BM=BN=128, K chunk = 64 bf16 (128 B/row), 3-stage cp.async pipeline
//   8 warps (2x4): each 64x32 via 4x4 m16n8k16 fragments; fp16 output (+T)
// ---------------------------------------------------------------------------
#define KC 64                        // bf16 elems per chunk (128 B per row)
#define NITER (DIM / KC)             // 8
#define ROWB 144                     // smem row stride (128B data + 16B pad)
#define STAGE_BYTES (2 * 128 * ROWB) // 36864
#define GSMEM (3 * STAGE_BYTES)      // 110592

__device__ __forceinline__ void load_stage(uint32_t sbase, int buf, int c,
                                           int tid, int bm, int bn) {
    uint32_t sA = sbase + buf * STAGE_BYTES;
    uint32_t sB = sA + 128 * ROWB;
    const char* gb = (const char*)g_hn;
    #pragma unroll
    for (int p = 0; p < 4; p++) {
        int i = tid + p * 256;
        int row = i >> 3, seg = i & 7;                  // 8 x 16B segs per row
        size_t koff = ((size_t)c * KC + seg * 8) * 2;   // bytes
        cp_async16(sA + row * ROWB + seg * 16, gb + (size_t)(bm + row) * DIM * 2 + koff);
        cp_async16(sB + row * ROWB + seg * 16, gb + (size_t)(bn + row) * DIM * 2 + koff);
    }
}

__global__ __launch_bounds__(256) void gemm_kernel() {
    const int I = blockIdx.y, J = blockIdx.x;
    if (J < I) return;                       // symmetric: upper triangle only
    const int bm = I * 128, bn = J * 128;

    extern __shared__ char smem[];
    const uint32_t sbase = smem_u32(smem);
    const int tid = threadIdx.x;
    const int lane = tid & 31;
    const int wid = tid >> 5;
    const int warpM = wid >> 2;              // 0..1 -> 64 rows
    const int warpN = wid & 3;               // 0..3 -> 32 cols

    float acc[4][4][4];
    #pragma unroll
    for (int mi = 0; mi < 4; mi++)
        #pragma unroll
        for (int ni = 0; ni < 4; ni++)
            #pragma unroll
            for (int q = 0; q < 4; q++) acc[mi][ni][q] = 0.0f;

    load_stage(sbase, 0, 0, tid, bm, bn); cp_commit();
    load_stage(sbase, 1, 1, tid, bm, bn); cp_commit();

    const uint32_t aLane = (uint32_t)((warpM * 64 + (lane & 15)) * ROWB + (lane >> 4) * 16);
    const uint32_t bLane = (uint32_t)(128 * ROWB + (warpN * 32 + (lane & 15)) * ROWB + (lane >> 4) * 16);

    for (int c = 0; c < NITER; c++) {
        if (c + 2 < NITER) cp_wait<1>(); else cp_wait<0>();
        __syncthreads();
        if (c + 2 < NITER) load_stage(sbase, (c + 2) % 3, c + 2, tid, bm, bn);
        cp_commit();

        const uint32_t sbuf = sbase + (c % 3) * STAGE_BYTES;
        #pragma unroll
        for (int ks = 0; ks < 4; ks++) {     // four k16 slices per 64-elem chunk
            uint32_t a[4][4], b[2][4];
            #pragma unroll
            for (int mi = 0; mi < 4; mi++)
                ldsm_x4(a[mi], sbuf + aLane + mi * (16 * ROWB) + ks * 32);
            #pragma unroll
            for (int nj = 0; nj < 2; nj++)
                ldsm_x4(b[nj], sbuf + bLane + nj * (16 * ROWB) + ks * 32);
            #pragma unroll
            for (int mi = 0; mi < 4; mi++)
                #pragma unroll
                for (int ni = 0; ni < 4; ni++) {
                    const int nj = ni >> 1, hi = ni & 1;
                    mma16816(acc[mi][ni], a[mi], b[nj][hi ? 1 : 0], b[nj][hi ? 3 : 2]);
                }
        }
    }

    // epilogue: fp16 store; off-diagonal tiles also store transposed
    const int r0 = bm + warpM * 64 + (lane >> 2);
    const int c0 = bn + warpN * 32 + (lane & 3) * 2;
    const bool offdiag = (I != J);
    #pragma unroll
    for (int mi = 0; mi < 4; mi++) {
        #pragma unroll
        for (int ni = 0; ni < 4; ni++) {
            const int r = r0 + mi * 16;
            const int cc = c0 + ni * 8;
            float d0 = acc[mi][ni][0], d1 = acc[mi][ni][1];
            float d2 = acc[mi][ni][2], d3 = acc[mi][ni][3];
            *reinterpret_cast<__half2*>(g_sim + (size_t)r * NROWS + cc) =
                make_half2(__float2half_rn(d0), __float2half_rn(d1));
            *reinterpret_cast<__half2*>(g_sim + (size_t)(r + 8) * NROWS + cc) =
                make_half2(__float2half_rn(d2), __float2half_rn(d3));
            if (offdiag) {
                __half* q0 = g_sim + (size_t)cc * NROWS + r;
                __half* q1 = g_sim + (size_t)(cc + 1) * NROWS + r;
                q0[0] = __float2half_rn(d0); q1[0] = __float2half_rn(d1);
                q0[8] = __float2half_rn(d2); q1[8] = __float2half_rn(d3);
            }
        }
    }
}

// ---------------------------------------------------------------------------
// Kernel 3: per-row top-12 (fp16 sims) -> softmax -> weighted gather of h
// ---------------------------------------------------------------------------
__global__ __launch_bounds__(256) void topk_kernel(const float* __restrict__ h,
                                                   float* __restrict__ out) {
    int row = blockIdx.x;
    int tid = threadIdx.x;
    const __half* sim = g_sim + (size_t)row * NROWS;

    float v[TOPK]; int ix[TOPK];
    #pragma unroll
    for (int k = 0; k < TOPK; k++) { v[k] = -INFINITY; ix[k] = 0x7FFFFFFF; }

    #pragma unroll
    for (int t = 0; t < 4; t++) {
        int base8 = t * 256 + tid;               // uint4 index (8 halfs)
        uint4 u = reinterpret_cast<const uint4*>(sim)[base8];
        int j0 = base8 * 8;
        uint32_t w[4] = {u.x, u.y, u.z, u.w};
        #pragma unroll
        for (int e = 0; e < 8; e++) {
            __half hv = ((const __half*)w)[e];
            float val = __half2float(hv);
            if (val > v[TOPK - 1]) {
                int p = TOPK - 1;
                #pragma unroll
                for (int s = TOPK - 1; s > 0; s--) {
                    if (v[s - 1] < val) { v[s] = v[s - 1]; ix[s] = ix[s - 1]; p = s - 1; }
                }
                v[p] = val; ix[p] = j0 + e;
            }
        }
    }

    __shared__ float sV[256][TOPK];
    __shared__ int   sI[256][TOPK];
    #pragma unroll
    for (int k = 0; k < TOPK; k++) { sV[tid][k] = v[k]; sI[tid][k] = ix[k]; }

    for (int stride = 128; stride > 0; stride >>= 1) {
        __syncthreads();
        if (tid < stride) {
            float mv[TOPK]; int mi[TOPK];
            int a = 0, b = 0;
            #pragma unroll
            for (int k = 0; k < TOPK; k++) {
                float va = sV[tid][a], vb = sV[tid + stride][b];
                int   ia = sI[tid][a], ib = sI[tid + stride][b];
                bool takeA = (va > vb) || (va == vb && ia < ib);
                if (takeA) { mv[k] = va; mi[k] = ia; a++; }
                else       { mv[k] = vb; mi[k] = ib; b++; }
            }
            #pragma unroll
            for (int k = 0; k < TOPK; k++) { sV[tid][k] = mv[k]; sI[tid][k] = mi[k]; }
        }
    }
    __syncthreads();

    __shared__ float sBeta[TOPK];
    __shared__ int   sIdx[TOPK];
    if (tid == 0) {
        float m = sV[0][0];
        float e[TOPK], sum = 0.0f;
        #pragma unroll
        for (int k = 0; k < TOPK; k++) { e[k] = expf(THETA * (sV[0][k] - m)); sum += e[k]; }
        float inv = 1.0f / sum;
        #pragma unroll
        for (int k = 0; k < TOPK; k++) { sBeta[k] = e[k] * inv; sIdx[k] = sI[0][k]; }
    }
    __syncthreads();

    float beta[TOPK]; const float* hp[TOPK];
    #pragma unroll
    for (int k = 0; k < TOPK; k++) { beta[k] = sBeta[k]; hp[k] = h + (size_t)sIdx[k] * DIM; }

    #pragma unroll
    for (int d = tid; d < DIM; d += 256) {
        float acc = 0.0f;
        #pragma unroll
        for (int k = 0; k < TOPK; k++) acc += beta[k] * hp[k][d];
        out[(size_t)row * DIM + d] = acc;
    }
}

// ---------------------------------------------------------------------------
extern "C" void kernel_launch(void* const* d_in, const int* in_sizes, int n_in,
                              void* d_out, int out_size) {
    const float* h = (const float*)d_in[0];
    float* out = (float*)d_out;

    cudaFuncSetAttribute(gemm_kernel, cudaFuncAttributeMaxDynamicSharedMemorySize, GSMEM);

    norm_kernel<<<NROWS, 256>>>(h);
    gemm_kernel<<<dim3(NROWS / 128, NROWS / 128), 256, GSMEM>>>();
    topk_kernel<<<NROWS, 256>>>(h, out);
}

// round 15
// speedup vs baseline: 2.0271x; 1.0071x over previous
#include <cuda_runtime.h>
#include <cuda_bf16.h>
#include <cuda_fp16.h>
#include <math.h>
#include <cstdint>

#define NROWS 8192
#define DIM   512
#define TOPK  12
#define THETA 10.0f

// ---------------- device scratch (no allocation allowed) -------------------
__device__ __nv_bfloat16 g_hn[NROWS * DIM];              // 8 MB normalized bf16
__device__ __half g_sim[(size_t)NROWS * NROWS];          // 128 MB similarity

__device__ __forceinline__ uint32_t smem_u32(const void* p) {
    uint32_t a;
    asm("{ .reg .u64 t; cvta.to.shared.u64 t, %1; cvt.u32.u64 %0, t; }"
        : "=r"(a) : "l"(p));
    return a;
}
__device__ __forceinline__ void cp_async16(uint32_t dst, const void* src) {
    asm volatile("cp.async.cg.shared.global [%0], [%1], 16;" :: "r"(dst), "l"(src));
}
__device__ __forceinline__ void cp_commit() {
    asm volatile("cp.async.commit_group;" ::: "memory");
}
template <int N>
__device__ __forceinline__ void cp_wait() {
    asm volatile("cp.async.wait_group %0;" :: "n"(N) : "memory");
}
__device__ __forceinline__ void ldsm_x4(uint32_t* r, uint32_t addr) {
    asm volatile("ldmatrix.sync.aligned.m8n8.x4.shared.b16 {%0,%1,%2,%3}, [%4];"
                 : "=r"(r[0]), "=r"(r[1]), "=r"(r[2]), "=r"(r[3]) : "r"(addr));
}
__device__ __forceinline__ void mma16816(float* c, const uint32_t* a,
                                         uint32_t b0, uint32_t b1) {
    asm volatile(
        "mma.sync.aligned.m16n8k16.row.col.f32.bf16.bf16.f32 "
        "{%0,%1,%2,%3}, {%4,%5,%6,%7}, {%8,%9}, {%0,%1,%2,%3};"
        : "+f"(c[0]), "+f"(c[1]), "+f"(c[2]), "+f"(c[3])
        : "r"(a[0]), "r"(a[1]), "r"(a[2]), "r"(a[3]), "r"(b0), "r"(b1));
}

// ---------------------------------------------------------------------------
// Kernel 1: row L2 norms -> normalized bf16 rows
// ---------------------------------------------------------------------------
__global__ __launch_bounds__(256) void norm_kernel(const float* __restrict__ h) {
    int row = blockIdx.x;
    int tid = threadIdx.x;
    const float* hr = h + (size_t)row * DIM;

    float v0 = hr[tid];
    float v1 = hr[tid + 256];
    float s = v0 * v0 + v1 * v1;
    #pragma unroll
    for (int off = 16; off > 0; off >>= 1) s += __shfl_xor_sync(~0u, s, off);

    __shared__ float red[8];
    if ((tid & 31) == 0) red[tid >> 5] = s;
    __syncthreads();
    if (tid < 32) {
        float t = (tid < 8) ? red[tid] : 0.0f;
        #pragma unroll
        for (int off = 4; off > 0; off >>= 1) t += __shfl_xor_sync(~0u, t, off);
        if (tid == 0) red[0] = t;
    }
    __syncthreads();
    float inv = 1.0f / fmaxf(sqrtf(red[0]), 1e-8f);
    g_hn[(size_t)row * DIM + tid]       = __float2bfloat16(v0 * inv);
    g_hn[(size_t)row * DIM + tid + 256] = __float2bfloat16(v1 * inv);
}

// ---------------------------------------------------------------------------
// Kernel 2: Sim = hn @ hn^T, upper-triangular tiles only, HMMA bf16
//   BM=BN=128, K chunk = 64 bf16, 3-stage cp.async pipeline, 2 CTAs/SM
// ---------------------------------------------------------------------------
#define KC 64                        // bf16 elems per chunk (128 B per row)
#define NITER (DIM / KC)             // 8
#define ROWB 144                     // smem row stride (128B data + 16B pad)
#define STAGE_BYTES (2 * 128 * ROWB) // 36864
#define GSMEM (3 * STAGE_BYTES)      // 110592 (x2 CTAs = 221184 <= 228KB/SM)

__device__ __forceinline__ void load_stage(uint32_t sbase, int buf, int c,
                                           int tid, int bm, int bn) {
    uint32_t sA = sbase + buf * STAGE_BYTES;
    uint32_t sB = sA + 128 * ROWB;
    const char* gb = (const char*)g_hn;
    #pragma unroll
    for (int p = 0; p < 4; p++) {
        int i = tid + p * 256;
        int row = i >> 3, seg = i & 7;                  // 8 x 16B segs per row
        size_t koff = ((size_t)c * KC + seg * 8) * 2;   // bytes
        cp_async16(sA + row * ROWB + seg * 16, gb + (size_t)(bm + row) * DIM * 2 + koff);
        cp_async16(sB + row * ROWB + seg * 16, gb + (size_t)(bn + row) * DIM * 2 + koff);
    }
}

__global__ __launch_bounds__(256, 2) void gemm_kernel() {
    const int I = blockIdx.y, J = blockIdx.x;
    if (J < I) return;                       // symmetric: upper triangle only
    const int bm = I * 128, bn = J * 128;

    extern __shared__ char smem[];
    const uint32_t sbase = smem_u32(smem);
    const int tid = threadIdx.x;
    const int lane = tid & 31;
    const int wid = tid >> 5;
    const int warpM = wid >> 2;              // 0..1 -> 64 rows
    const int warpN = wid & 3;               // 0..3 -> 32 cols

    float acc[4][4][4];
    #pragma unroll
    for (int mi = 0; mi < 4; mi++)
        #pragma unroll
        for (int ni = 0; ni < 4; ni++)
            #pragma unroll
            for (int q = 0; q < 4; q++) acc[mi][ni][q] = 0.0f;

    load_stage(sbase, 0, 0, tid, bm, bn); cp_commit();
    load_stage(sbase, 1, 1, tid, bm, bn); cp_commit();

    const uint32_t aLane = (uint32_t)((warpM * 64 + (lane & 15)) * ROWB + (lane >> 4) * 16);
    const uint32_t bLane = (uint32_t)(128 * ROWB + (warpN * 32 + (lane & 15)) * ROWB + (lane >> 4) * 16);

    for (int c = 0; c < NITER; c++) {
        if (c + 2 < NITER) cp_wait<1>(); else cp_wait<0>();
        __syncthreads();
        if (c + 2 < NITER) load_stage(sbase, (c + 2) % 3, c + 2, tid, bm, bn);
        cp_commit();

        const uint32_t sbuf = sbase + (c % 3) * STAGE_BYTES;
        #pragma unroll
        for (int ks = 0; ks < 4; ks++) {     // four k16 slices per 64-elem chunk
            uint32_t a[4][4], b[2][4];
            #pragma unroll
            for (int mi = 0; mi < 4; mi++)
                ldsm_x4(a[mi], sbuf + aLane + mi * (16 * ROWB) + ks * 32);
            #pragma unroll
            for (int nj = 0; nj < 2; nj++)
                ldsm_x4(b[nj], sbuf + bLane + nj * (16 * ROWB) + ks * 32);
            #pragma unroll
            for (int mi = 0; mi < 4; mi++)
                #pragma unroll
                for (int ni = 0; ni < 4; ni++) {
                    const int nj = ni >> 1, hi = ni & 1;
                    mma16816(acc[mi][ni], a[mi], b[nj][hi ? 1 : 0], b[nj][hi ? 3 : 2]);
                }
        }
    }

    // epilogue: fp16 store; off-diagonal tiles also store transposed
    const int r0 = bm + warpM * 64 + (lane >> 2);
    const int c0 = bn + warpN * 32 + (lane & 3) * 2;
    const bool offdiag = (I != J);
    #pragma unroll
    for (int mi = 0; mi < 4; mi++) {
        #pragma unroll
        for (int ni = 0; ni < 4; ni++) {
            const int r = r0 + mi * 16;
            const int cc = c0 + ni * 8;
            float d0 = acc[mi][ni][0], d1 = acc[mi][ni][1];
            float d2 = acc[mi][ni][2], d3 = acc[mi][ni][3];
            *reinterpret_cast<__half2*>(g_sim + (size_t)r * NROWS + cc) =
                make_half2(__float2half_rn(d0), __float2half_rn(d1));
            *reinterpret_cast<__half2*>(g_sim + (size_t)(r + 8) * NROWS + cc) =
                make_half2(__float2half_rn(d2), __float2half_rn(d3));
            if (offdiag) {
                __half* q0 = g_sim + (size_t)cc * NROWS + r;
                __half* q1 = g_sim + (size_t)(cc + 1) * NROWS + r;
                q0[0] = __float2half_rn(d0); q1[0] = __float2half_rn(d1);
                q0[8] = __float2half_rn(d2); q1[8] = __float2half_rn(d3);
            }
        }
    }
}

// ---------------------------------------------------------------------------
// Kernel 3: per-row top-12 (fp16 sims) -> softmax -> weighted gather of h
// ---------------------------------------------------------------------------
__global__ __launch_bounds__(256) void topk_kernel(const float* __restrict__ h,
                                                   float* __restrict__ out) {
    int row = blockIdx.x;
    int tid = threadIdx.x;
    const __half* sim = g_sim + (size_t)row * NROWS;

    float v[TOPK]; int ix[TOPK];
    #pragma unroll
    for (int k = 0; k < TOPK; k++) { v[k] = -INFINITY; ix[k] = 0x7FFFFFFF; }

    #pragma unroll
    for (int t = 0; t < 4; t++) {
        int base8 = t * 256 + tid;               // uint4 index (8 halfs)
        uint4 u = reinterpret_cast<const uint4*>(sim)[base8];
        int j0 = base8 * 8;
        uint32_t w[4] = {u.x, u.y, u.z, u.w};
        #pragma unroll
        for (int e = 0; e < 8; e++) {
            __half hv = ((const __half*)w)[e];
            float val = __half2float(hv);
            if (val > v[TOPK - 1]) {
                int p = TOPK - 1;
                #pragma unroll
                for (int s = TOPK - 1; s > 0; s--) {
                    if (v[s - 1] < val) { v[s] = v[s - 1]; ix[s] = ix[s - 1]; p = s - 1; }
                }
                v[p] = val; ix[p] = j0 + e;
            }
        }
    }

    __shared__ float sV[256][TOPK];
    __shared__ int   sI[256][TOPK];
    #pragma unroll
    for (int k = 0; k < TOPK; k++) { sV[tid][k] = v[k]; sI[tid][k] = ix[k]; }

    for (int stride = 128; stride > 0; stride >>= 1) {
        __syncthreads();
        if (tid < stride) {
            float mv[TOPK]; int mi[TOPK];
            int a = 0, b = 0;
            #pragma unroll
            for (int k = 0; k < TOPK; k++) {
                float va = sV[tid][a], vb = sV[tid + stride][b];
                int   ia = sI[tid][a], ib = sI[tid + stride][b];
                bool takeA = (va > vb) || (va == vb && ia < ib);
                if (takeA) { mv[k] = va; mi[k] = ia; a++; }
                else       { mv[k] = vb; mi[k] = ib; b++; }
            }
            #pragma unroll
            for (int k = 0; k < TOPK; k++) { sV[tid][k] = mv[k]; sI[tid][k] = mi[k]; }
        }
    }
    __syncthreads();

    __shared__ float sBeta[TOPK];
    __shared__ int   sIdx[TOPK];
    if (tid == 0) {
        float m = sV[0][0];
        float e[TOPK], sum = 0.0f;
        #pragma unroll
        for (int k = 0; k < TOPK; k++) { e[k] = expf(THETA * (sV[0][k] - m)); sum += e[k]; }
        float inv = 1.0f / sum;
        #pragma unroll
        for (int k = 0; k < TOPK; k++) { sBeta[k] = e[k] * inv; sIdx[k] = sI[0][k]; }
    }
    __syncthreads();

    float beta[TOPK]; const float* hp[TOPK];
    #pragma unroll
    for (int k = 0; k < TOPK; k++) { beta[k] = sBeta[k]; hp[k] = h + (size_t)sIdx[k] * DIM; }

    #pragma unroll
    for (int d = tid; d < DIM; d += 256) {
        float acc = 0.0f;
        #pragma unroll
        for (int k = 0; k < TOPK; k++) acc += beta[k] * hp[k][d];
        out[(size_t)row * DIM + d] = acc;
    }
}

// ---------------------------------------------------------------------------
extern "C" void kernel_launch(void* const* d_in, const int* in_sizes, int n_in,
                              void* d_out, int out_size) {
    const float* h = (const float*)d_in[0];
    float* out = (float*)d_out;

    cudaFuncSetAttribute(gemm_kernel, cudaFuncAttributeMaxDynamicSharedMemorySize, GSMEM);

    norm_kernel<<<NROWS, 256>>>(h);
    gemm_kernel<<<dim3(NROWS / 128, NROWS / 128), 256, GSMEM>>>();
    topk_kernel<<<NROWS, 256>>>(h, out);
}